// round 2
// baseline (speedup 1.0000x reference)
#include <cuda_runtime.h>
#include <cuda_bf16.h>
#include <math.h>

// Problem constants (fixed by the dataset)
#define NMAX 100000
#define EMAX 3200000
#define IN_F 128
#define HID 64
#define CAT 192   // HID * 3 powers
#define OUT_F 40
#define LN_EPS 1e-5f

// ---------------- device scratch (static, no allocation) ----------------
__device__ int   g_deg[NMAX];
__device__ int   g_rowptr[NMAX + 1];
__device__ int   g_cursor[NMAX];
__device__ int   g_csrc[EMAX + NMAX];
__device__ float g_dis[NMAX];
__device__ float g_hA[NMAX * HID];
__device__ float g_hB[NMAX * HID];
__device__ float g_hcat[NMAX * CAT];

__device__ __forceinline__ float gelu_exact(float x) {
    return 0.5f * x * (1.0f + erff(x * 0.70710678118654752f));
}

// ---------------- graph preprocessing ----------------
__global__ void k_init_deg(int n) {
    int i = blockIdx.x * blockDim.x + threadIdx.x;
    if (i < n) g_deg[i] = 1;  // self loop
}

__global__ void k_hist(const int* __restrict__ ei, int e) {
    int i = blockIdx.x * blockDim.x + threadIdx.x;
    if (i < e) atomicAdd(&g_deg[ei[e + i]], 1);  // dst row of edge_index
}

__global__ void k_dis(int n) {
    int i = blockIdx.x * blockDim.x + threadIdx.x;
    if (i < n) g_dis[i] = rsqrtf((float)g_deg[i]);
}

// exclusive scan of g_deg -> g_rowptr / g_cursor, single block, shfl-based
__global__ void k_scan(int n) {
    __shared__ int wsum[32];
    __shared__ int woff[32];
    __shared__ int carry_s;
    int tid = threadIdx.x, lane = tid & 31, wid = tid >> 5;
    if (tid == 0) carry_s = 0;
    __syncthreads();
    for (int base = 0; base < n; base += 1024) {
        int idx = base + tid;
        int v = (idx < n) ? g_deg[idx] : 0;
        int orig = v;
        #pragma unroll
        for (int o = 1; o < 32; o <<= 1) {
            int t = __shfl_up_sync(0xffffffffu, v, o);
            if (lane >= o) v += t;
        }
        if (lane == 31) wsum[wid] = v;
        __syncthreads();
        if (wid == 0) {
            int u = wsum[lane];
            int s = u;
            #pragma unroll
            for (int o = 1; o < 32; o <<= 1) {
                int t = __shfl_up_sync(0xffffffffu, s, o);
                if (lane >= o) s += t;
            }
            woff[lane] = s - u;           // exclusive warp offsets
            if (lane == 31) wsum[0] = s;  // chunk total (reads of wsum done)
        }
        __syncthreads();
        int excl = (v - orig) + woff[wid] + carry_s;
        if (idx < n) { g_rowptr[idx] = excl; g_cursor[idx] = excl; }
        __syncthreads();
        if (tid == 0) carry_s += wsum[0];
        __syncthreads();
    }
    if (threadIdx.x == 0) g_rowptr[n] = carry_s;
}

__global__ void k_scatter(const int* __restrict__ ei, int e, int n) {
    int i = blockIdx.x * blockDim.x + threadIdx.x;
    if (i < e) {
        int s = ei[i], d = ei[e + i];
        int pos = atomicAdd(&g_cursor[d], 1);
        g_csrc[pos] = s;
    } else if (i < e + n) {
        int v = i - e;
        int pos = atomicAdd(&g_cursor[v], 1);
        g_csrc[pos] = v;  // self loop
    }
}

// ---------------- layer 1 GEMM: hA = x @ W1 + b1 (N x 128 x 64) ----------------
__global__ void __launch_bounds__(256) k_gemm1(const float* __restrict__ x,
                                               const float* __restrict__ W1,
                                               const float* __restrict__ b1, int n) {
    __shared__ float xs[64][65];
    __shared__ float ws[64 * 64];
    int tid = threadIdx.x;
    int node0 = blockIdx.x * 64;
    int r = tid >> 2, q = tid & 3;
    float acc[16];
    #pragma unroll
    for (int j = 0; j < 16; j++) acc[j] = 0.f;
    for (int kc = 0; kc < 2; kc++) {
        __syncthreads();
        for (int i = tid; i < 4096; i += 256) ws[i] = W1[kc * 4096 + i];
        for (int i = tid; i < 4096; i += 256) {
            int rr = i >> 6, cc = i & 63;
            int gn = node0 + rr;
            xs[rr][cc] = (gn < n) ? x[gn * IN_F + kc * 64 + cc] : 0.f;
        }
        __syncthreads();
        #pragma unroll 8
        for (int k = 0; k < 64; k++) {
            float xv = xs[r][k];
            const float* wrow = &ws[k * 64];
            #pragma unroll
            for (int j = 0; j < 16; j++) acc[j] = fmaf(xv, wrow[q + 4 * j], acc[j]);
        }
    }
    int gn = node0 + r;
    if (gn < n) {
        #pragma unroll
        for (int j = 0; j < 16; j++) {
            int c = q + 4 * j;
            g_hA[gn * HID + c] = acc[j] + b1[c];
        }
    }
}

// gelu + LayerNorm(64) in place on g_hA, one warp per node
__global__ void __launch_bounds__(256) k_gln64(const float* __restrict__ g1,
                                               const float* __restrict__ be1, int n) {
    int warp = (blockIdx.x * blockDim.x + threadIdx.x) >> 5;
    int lane = threadIdx.x & 31;
    if (warp >= n) return;
    float2 v = ((const float2*)g_hA)[warp * 32 + lane];
    v.x = gelu_exact(v.x);
    v.y = gelu_exact(v.y);
    float s = v.x + v.y, ss = v.x * v.x + v.y * v.y;
    #pragma unroll
    for (int o = 16; o; o >>= 1) {
        s  += __shfl_xor_sync(0xffffffffu, s, o);
        ss += __shfl_xor_sync(0xffffffffu, ss, o);
    }
    float mu = s * (1.f / 64.f);
    float var = ss * (1.f / 64.f) - mu * mu;
    float r = rsqrtf(var + LN_EPS);
    int c = 2 * lane;
    float2 o2;
    o2.x = (v.x - mu) * r * g1[c] + be1[c];
    o2.y = (v.y - mu) * r * g1[c + 1] + be1[c + 1];
    ((float2*)g_hA)[warp * 32 + lane] = o2;
}

// ---------------- SpMM hop: warp per dst row, zero atomics ----------------
// dir==0: A -> B ; dir==1: B -> A
__global__ void __launch_bounds__(256) k_spmm(int dir, int n) {
    int warp = (blockIdx.x * blockDim.x + threadIdx.x) >> 5;
    int lane = threadIdx.x & 31;
    if (warp >= n) return;
    const float2* __restrict__ hin  = dir ? (const float2*)g_hB : (const float2*)g_hA;
    float2* __restrict__ hout       = dir ? (float2*)g_hA : (float2*)g_hB;
    int beg = g_rowptr[warp], end = g_rowptr[warp + 1];
    float dn = g_dis[warp];
    float2 acc = make_float2(0.f, 0.f);
    int e = beg;
    // unroll by 2 for memory-level parallelism
    for (; e + 1 < end; e += 2) {
        int s0 = __ldg(&g_csrc[e]);
        int s1 = __ldg(&g_csrc[e + 1]);
        float w0 = dn * __ldg(&g_dis[s0]);
        float w1 = dn * __ldg(&g_dis[s1]);
        float2 v0 = __ldg(&hin[s0 * 32 + lane]);
        float2 v1 = __ldg(&hin[s1 * 32 + lane]);
        acc.x = fmaf(w0, v0.x, acc.x);
        acc.y = fmaf(w0, v0.y, acc.y);
        acc.x = fmaf(w1, v1.x, acc.x);
        acc.y = fmaf(w1, v1.y, acc.y);
    }
    if (e < end) {
        int s0 = __ldg(&g_csrc[e]);
        float w0 = dn * __ldg(&g_dis[s0]);
        float2 v0 = __ldg(&hin[s0 * 32 + lane]);
        acc.x = fmaf(w0, v0.x, acc.x);
        acc.y = fmaf(w0, v0.y, acc.y);
    }
    hout[warp * 32 + lane] = acc;
}

// ---------------- per-power GEMM: hcat[:, off:off+64] = cur @ Wc[p] + bc[p] ----------------
__global__ void __launch_bounds__(256) k_mix(int src, const float* __restrict__ Wc,
                                             const float* __restrict__ bc, int off, int n) {
    __shared__ float xs[64][65];
    __shared__ float ws[64 * 64];
    const float* __restrict__ hin = src ? g_hB : g_hA;
    int tid = threadIdx.x;
    int node0 = blockIdx.x * 64;
    for (int i = tid; i < 4096; i += 256) ws[i] = Wc[i];
    for (int i = tid; i < 4096; i += 256) {
        int rr = i >> 6, cc = i & 63;
        int gn = node0 + rr;
        xs[rr][cc] = (gn < n) ? hin[gn * HID + cc] : 0.f;
    }
    __syncthreads();
    int r = tid >> 2, q = tid & 3;
    float acc[16];
    #pragma unroll
    for (int j = 0; j < 16; j++) acc[j] = 0.f;
    #pragma unroll 8
    for (int k = 0; k < 64; k++) {
        float xv = xs[r][k];
        const float* wrow = &ws[k * 64];
        #pragma unroll
        for (int j = 0; j < 16; j++) acc[j] = fmaf(xv, wrow[q + 4 * j], acc[j]);
    }
    int gn = node0 + r;
    if (gn < n) {
        #pragma unroll
        for (int j = 0; j < 16; j++) {
            int c = q + 4 * j;
            g_hcat[gn * CAT + off + c] = acc[j] + bc[c];
        }
    }
}

// ---------------- final: gelu + LN(192) + GEMM(192x40) ----------------
__global__ void __launch_bounds__(256) k_final(const float* __restrict__ W2,
                                               const float* __restrict__ b2,
                                               const float* __restrict__ g2,
                                               const float* __restrict__ be2,
                                               float* __restrict__ out, int n) {
    __shared__ float w2s[CAT * OUT_F];
    __shared__ float b2s[OUT_F];
    __shared__ float sv[8][CAT];
    int tid = threadIdx.x;
    for (int i = tid; i < CAT * OUT_F; i += 256) w2s[i] = W2[i];
    if (tid < OUT_F) b2s[tid] = b2[tid];
    __syncthreads();
    int wrp = tid >> 5, lane = tid & 31;
    int node = blockIdx.x * 8 + wrp;
    if (node >= n) return;
    float v[6];
    float s = 0.f, ss = 0.f;
    #pragma unroll
    for (int i = 0; i < 6; i++) {
        float t = g_hcat[node * CAT + i * 32 + lane];
        t = gelu_exact(t);
        v[i] = t;
        s += t;
        ss += t * t;
    }
    #pragma unroll
    for (int o = 16; o; o >>= 1) {
        s  += __shfl_xor_sync(0xffffffffu, s, o);
        ss += __shfl_xor_sync(0xffffffffu, ss, o);
    }
    float mu = s * (1.f / 192.f);
    float var = ss * (1.f / 192.f) - mu * mu;
    float r = rsqrtf(var + LN_EPS);
    #pragma unroll
    for (int i = 0; i < 6; i++) {
        int k = i * 32 + lane;
        sv[wrp][k] = (v[i] - mu) * r * g2[k] + be2[k];
    }
    __syncwarp();
    for (int c = lane; c < OUT_F; c += 32) {
        float a = b2s[c];
        #pragma unroll 8
        for (int k = 0; k < CAT; k++) a = fmaf(sv[wrp][k], w2s[k * OUT_F + c], a);
        out[node * OUT_F + c] = a;
    }
}

// ---------------- host launcher ----------------
extern "C" void kernel_launch(void* const* d_in, const int* in_sizes, int n_in,
                              void* d_out, int out_size) {
    const float* x  = (const float*)d_in[0];
    const int*   ei = (const int*)d_in[1];
    const float* W1 = (const float*)d_in[2];
    const float* b1 = (const float*)d_in[3];
    const float* Wc = (const float*)d_in[4];
    const float* bc = (const float*)d_in[5];
    const float* W2 = (const float*)d_in[6];
    const float* b2 = (const float*)d_in[7];
    const float* g1 = (const float*)d_in[8];
    const float* be1= (const float*)d_in[9];
    const float* g2 = (const float*)d_in[10];
    const float* be2= (const float*)d_in[11];
    float* out = (float*)d_out;

    int n = in_sizes[0] / IN_F;   // nodes
    int e = in_sizes[1] / 2;      // edges

    // graph preprocessing (rebuilt deterministically each call)
    k_init_deg<<<(n + 255) / 256, 256>>>(n);
    k_hist<<<(e + 255) / 256, 256>>>(ei, e);
    k_dis<<<(n + 255) / 256, 256>>>(n);
    k_scan<<<1, 1024>>>(n);
    k_scatter<<<(e + n + 255) / 256, 256>>>(ei, e, n);

    // layer 1
    k_gemm1<<<(n + 63) / 64, 256>>>(x, W1, b1, n);
    int wgrid = (n + 7) / 8;  // 8 warps per 256-thread block
    k_gln64<<<wgrid, 256>>>(g1, be1, n);

    // 10 propagation hops; cur starts in A.
    // after hop j: cur in B if j odd, A if j even.
    int dir = 0;
    for (int j = 1; j <= 10; j++) {
        k_spmm<<<wgrid, 256>>>(dir, n);
        int curInB = (dir == 0);  // just wrote into B if dir==0
        dir ^= 1;
        if (j == 6)  k_mix<<<(n + 63) / 64, 256>>>(curInB ? 1 : 0, Wc + 6 * HID * HID,  bc + 6 * HID,  0,   n);
        if (j == 8)  k_mix<<<(n + 63) / 64, 256>>>(curInB ? 1 : 0, Wc + 8 * HID * HID,  bc + 8 * HID,  64,  n);
        if (j == 10) k_mix<<<(n + 63) / 64, 256>>>(curInB ? 1 : 0, Wc + 10 * HID * HID, bc + 10 * HID, 128, n);
    }

    k_final<<<wgrid, 256>>>(W2, b2, g2, be2, out, n);
}

// round 3
// speedup vs baseline: 1.1434x; 1.1434x over previous
#include <cuda_runtime.h>
#include <cuda_fp16.h>
#include <math.h>

#define NMAX 100000
#define EMAX 3200000
#define IN_F 128
#define HID 64
#define CAT 192
#define OUT_F 40
#define LN_EPS 1e-5f
#define NBMAX 128   // ceil(NMAX/1024)

// ---------------- device scratch ----------------
__device__ int     g_deg[NMAX];
__device__ int     g_rowptr[NMAX + 1];
__device__ int     g_cursor[NMAX];
__device__ int     g_csrc[EMAX + NMAX];
__device__ int     g_bsum[NBMAX];
__device__ int     g_boff[NBMAX];
__device__ float   g_dis[NMAX];      // deg^-1/2
__device__ float   g_sdeg[NMAX];     // deg^+1/2
__device__ float   g_invdeg[NMAX];   // 1/deg
__device__ __half2 g_uA[NMAX * 32];  // u = D^-1/2 h, fp16
__device__ __half2 g_uB[NMAX * 32];
__device__ float   g_hcat[NMAX * CAT];

__device__ __forceinline__ float gelu_exact(float x) {
    return 0.5f * x * (1.0f + erff(x * 0.70710678118654752f));
}

// ---------------- preprocessing ----------------
__global__ void k_init_deg(int n) {
    int i = blockIdx.x * blockDim.x + threadIdx.x;
    if (i < n) g_deg[i] = 1;  // self loop
}

__global__ void k_hist(const int* __restrict__ ei, int e) {
    int i = blockIdx.x * blockDim.x + threadIdx.x;
    if (i < e) atomicAdd(&g_deg[ei[e + i]], 1);
}

__global__ void k_aux(int n) {
    int i = blockIdx.x * blockDim.x + threadIdx.x;
    if (i < n) {
        float d = (float)g_deg[i];
        g_dis[i] = rsqrtf(d);
        g_sdeg[i] = sqrtf(d);
        g_invdeg[i] = 1.0f / d;
    }
}

// scan stage 1: per-block (1024 elems) sums
__global__ void __launch_bounds__(1024) k_blocksum(int n) {
    __shared__ int ws[32];
    int tid = threadIdx.x, lane = tid & 31, wid = tid >> 5;
    int idx = blockIdx.x * 1024 + tid;
    int v = (idx < n) ? g_deg[idx] : 0;
    #pragma unroll
    for (int o = 16; o; o >>= 1) v += __shfl_xor_sync(0xffffffffu, v, o);
    if (lane == 0) ws[wid] = v;
    __syncthreads();
    if (wid == 0) {
        int u = ws[lane];
        #pragma unroll
        for (int o = 16; o; o >>= 1) u += __shfl_xor_sync(0xffffffffu, u, o);
        if (lane == 0) g_bsum[blockIdx.x] = u;
    }
}

// scan stage 2: one warp scans up to NBMAX block sums (exclusive)
__global__ void k_scanbsums(int nb) {
    int lane = threadIdx.x;
    int carry = 0;
    for (int base = 0; base < nb; base += 32) {
        int idx = base + lane;
        int v = (idx < nb) ? g_bsum[idx] : 0;
        int orig = v;
        #pragma unroll
        for (int o = 1; o < 32; o <<= 1) {
            int t = __shfl_up_sync(0xffffffffu, v, o);
            if (lane >= o) v += t;
        }
        if (idx < nb) g_boff[idx] = carry + v - orig;
        carry += __shfl_sync(0xffffffffu, v, 31);
    }
}

// scan stage 3: local exclusive scan + block offset
__global__ void __launch_bounds__(1024) k_scanlocal(int n, int total) {
    __shared__ int wsum[32], woff[32];
    int tid = threadIdx.x, lane = tid & 31, wid = tid >> 5;
    int idx = blockIdx.x * 1024 + tid;
    int v = (idx < n) ? g_deg[idx] : 0;
    int orig = v;
    #pragma unroll
    for (int o = 1; o < 32; o <<= 1) {
        int t = __shfl_up_sync(0xffffffffu, v, o);
        if (lane >= o) v += t;
    }
    if (lane == 31) wsum[wid] = v;
    __syncthreads();
    if (wid == 0) {
        int u = wsum[lane];
        int s = u;
        #pragma unroll
        for (int o = 1; o < 32; o <<= 1) {
            int t = __shfl_up_sync(0xffffffffu, s, o);
            if (lane >= o) s += t;
        }
        woff[lane] = s - u;
    }
    __syncthreads();
    int excl = (v - orig) + woff[wid] + g_boff[blockIdx.x];
    if (idx < n) { g_rowptr[idx] = excl; g_cursor[idx] = excl; }
    if (idx == 0) g_rowptr[n] = total;
}

__global__ void k_scatter(const int* __restrict__ ei, int e, int n) {
    int i = blockIdx.x * blockDim.x + threadIdx.x;
    if (i < e) {
        int s = ei[i], d = ei[e + i];
        int pos = atomicAdd(&g_cursor[d], 1);
        g_csrc[pos] = s;
    } else if (i < e + n) {
        int v = i - e;
        int pos = atomicAdd(&g_cursor[v], 1);
        g_csrc[pos] = v;
    }
}

// ---------------- layer1 GEMM + gelu + LN(64) + dis-scale -> fp16 u0 ----------------
__global__ void __launch_bounds__(256) k_gemm1(const float* __restrict__ x,
                                               const float* __restrict__ W1,
                                               const float* __restrict__ b1,
                                               const float* __restrict__ g1,
                                               const float* __restrict__ be1, int n) {
    __shared__ float xs[64][65];
    __shared__ float ws[64 * 64];
    int tid = threadIdx.x;
    int node0 = blockIdx.x * 64;
    int r = tid >> 2, q = tid & 3;
    float acc[16];
    #pragma unroll
    for (int j = 0; j < 16; j++) acc[j] = 0.f;
    for (int kc = 0; kc < 2; kc++) {
        __syncthreads();
        for (int i = tid; i < 4096; i += 256) ws[i] = W1[kc * 4096 + i];
        for (int i = tid; i < 4096; i += 256) {
            int rr = i >> 6, cc = i & 63;
            int gn = node0 + rr;
            xs[rr][cc] = (gn < n) ? x[gn * IN_F + kc * 64 + cc] : 0.f;
        }
        __syncthreads();
        #pragma unroll 8
        for (int k = 0; k < 64; k++) {
            float xv = xs[r][k];
            const float* wrow = &ws[k * 64];
            #pragma unroll
            for (int j = 0; j < 16; j++) acc[j] = fmaf(xv, wrow[q + 4 * j], acc[j]);
        }
    }
    // epilogue: bias + gelu + LN over the 4 lanes owning row r
    int gn = node0 + r;
    float s = 0.f, ss = 0.f;
    #pragma unroll
    for (int j = 0; j < 16; j++) {
        int c = q + 4 * j;
        float t = gelu_exact(acc[j] + b1[c]);
        acc[j] = t;
        s += t; ss += t * t;
    }
    s += __shfl_xor_sync(0xffffffffu, s, 1);
    s += __shfl_xor_sync(0xffffffffu, s, 2);
    ss += __shfl_xor_sync(0xffffffffu, ss, 1);
    ss += __shfl_xor_sync(0xffffffffu, ss, 2);
    float mu = s * (1.f / 64.f);
    float var = ss * (1.f / 64.f) - mu * mu;
    float rst = rsqrtf(var + LN_EPS);
    float dis = (gn < n) ? g_dis[gn] : 0.f;
    __syncthreads();
    #pragma unroll
    for (int j = 0; j < 16; j++) {
        int c = q + 4 * j;
        xs[r][c] = ((acc[j] - mu) * rst * g1[c] + be1[c]) * dis;
    }
    __syncthreads();
    for (int i = tid; i < 64 * 32; i += 256) {
        int rr = i >> 5, hc = i & 31;
        int g = node0 + rr;
        if (g < n) g_uA[g * 32 + hc] = __floats2half2_rn(xs[rr][2 * hc], xs[rr][2 * hc + 1]);
    }
}

// ---------------- SpMM hop on u: plain neighbor sum * invdeg, fp16 I/O ----------------
__global__ void __launch_bounds__(256) k_spmm(int dir, int n) {
    int warp = (blockIdx.x * blockDim.x + threadIdx.x) >> 5;
    int lane = threadIdx.x & 31;
    if (warp >= n) return;
    const __half2* __restrict__ hin = dir ? g_uB : g_uA;
    __half2* __restrict__ hout      = dir ? g_uA : g_uB;
    int beg = __ldg(&g_rowptr[warp]), end = __ldg(&g_rowptr[warp + 1]);
    float ax = 0.f, ay = 0.f;
    int e = beg;
    for (; e + 3 < end; e += 4) {
        int s0 = __ldg(&g_csrc[e]);
        int s1 = __ldg(&g_csrc[e + 1]);
        int s2 = __ldg(&g_csrc[e + 2]);
        int s3 = __ldg(&g_csrc[e + 3]);
        float2 v0 = __half22float2(__ldg(&hin[s0 * 32 + lane]));
        float2 v1 = __half22float2(__ldg(&hin[s1 * 32 + lane]));
        float2 v2 = __half22float2(__ldg(&hin[s2 * 32 + lane]));
        float2 v3 = __half22float2(__ldg(&hin[s3 * 32 + lane]));
        ax += (v0.x + v1.x) + (v2.x + v3.x);
        ay += (v0.y + v1.y) + (v2.y + v3.y);
    }
    for (; e < end; e++) {
        int s0 = __ldg(&g_csrc[e]);
        float2 v0 = __half22float2(__ldg(&hin[s0 * 32 + lane]));
        ax += v0.x; ay += v0.y;
    }
    float w = __ldg(&g_invdeg[warp]);
    hout[warp * 32 + lane] = __floats2half2_rn(ax * w, ay * w);
}

// ---------------- per-power GEMM: hcat[:,off:off+64] = (sdeg*u) @ Wc + bc ----------------
__global__ void __launch_bounds__(256) k_mix(int src, const float* __restrict__ Wc,
                                             const float* __restrict__ bc, int off, int n) {
    __shared__ float xs[64][65];
    __shared__ float ws[64 * 64];
    const __half2* __restrict__ u = src ? g_uB : g_uA;
    int tid = threadIdx.x;
    int node0 = blockIdx.x * 64;
    for (int i = tid; i < 4096; i += 256) ws[i] = Wc[i];
    for (int i = tid; i < 64 * 32; i += 256) {
        int rr = i >> 5, hc = i & 31;
        int gn = node0 + rr;
        float2 v = (gn < n) ? __half22float2(u[gn * 32 + hc]) : make_float2(0.f, 0.f);
        xs[rr][2 * hc] = v.x;
        xs[rr][2 * hc + 1] = v.y;
    }
    __syncthreads();
    int r = tid >> 2, q = tid & 3;
    float acc[16];
    #pragma unroll
    for (int j = 0; j < 16; j++) acc[j] = 0.f;
    #pragma unroll 8
    for (int k = 0; k < 64; k++) {
        float xv = xs[r][k];
        const float* wrow = &ws[k * 64];
        #pragma unroll
        for (int j = 0; j < 16; j++) acc[j] = fmaf(xv, wrow[q + 4 * j], acc[j]);
    }
    int gn = node0 + r;
    if (gn < n) {
        float sd = g_sdeg[gn];  // fold D^+1/2 back: h = sdeg * u
        #pragma unroll
        for (int j = 0; j < 16; j++) {
            int c = q + 4 * j;
            g_hcat[gn * CAT + off + c] = acc[j] * sd + bc[c];
        }
    }
}

// ---------------- final: gelu + LN(192) + GEMM(192x40) ----------------
__global__ void __launch_bounds__(256) k_final(const float* __restrict__ W2,
                                               const float* __restrict__ b2,
                                               const float* __restrict__ g2,
                                               const float* __restrict__ be2,
                                               float* __restrict__ out, int n) {
    __shared__ float w2s[CAT * OUT_F];
    __shared__ float b2s[OUT_F];
    __shared__ float sv[8][CAT];
    int tid = threadIdx.x;
    for (int i = tid; i < CAT * OUT_F; i += 256) w2s[i] = W2[i];
    if (tid < OUT_F) b2s[tid] = b2[tid];
    __syncthreads();
    int wrp = tid >> 5, lane = tid & 31;
    int node = blockIdx.x * 8 + wrp;
    if (node >= n) return;
    float v[6];
    float s = 0.f, ss = 0.f;
    #pragma unroll
    for (int i = 0; i < 6; i++) {
        float t = g_hcat[node * CAT + i * 32 + lane];
        t = gelu_exact(t);
        v[i] = t;
        s += t; ss += t * t;
    }
    #pragma unroll
    for (int o = 16; o; o >>= 1) {
        s  += __shfl_xor_sync(0xffffffffu, s, o);
        ss += __shfl_xor_sync(0xffffffffu, ss, o);
    }
    float mu = s * (1.f / 192.f);
    float var = ss * (1.f / 192.f) - mu * mu;
    float r = rsqrtf(var + LN_EPS);
    #pragma unroll
    for (int i = 0; i < 6; i++) {
        int k = i * 32 + lane;
        sv[wrp][k] = (v[i] - mu) * r * g2[k] + be2[k];
    }
    __syncwarp();
    for (int c = lane; c < OUT_F; c += 32) {
        float a = b2s[c];
        #pragma unroll 8
        for (int k = 0; k < CAT; k++) a = fmaf(sv[wrp][k], w2s[k * OUT_F + c], a);
        out[node * OUT_F + c] = a;
    }
}

// ---------------- host launcher ----------------
extern "C" void kernel_launch(void* const* d_in, const int* in_sizes, int n_in,
                              void* d_out, int out_size) {
    const float* x  = (const float*)d_in[0];
    const int*   ei = (const int*)d_in[1];
    const float* W1 = (const float*)d_in[2];
    const float* b1 = (const float*)d_in[3];
    const float* Wc = (const float*)d_in[4];
    const float* bc = (const float*)d_in[5];
    const float* W2 = (const float*)d_in[6];
    const float* b2 = (const float*)d_in[7];
    const float* g1 = (const float*)d_in[8];
    const float* be1= (const float*)d_in[9];
    const float* g2 = (const float*)d_in[10];
    const float* be2= (const float*)d_in[11];
    float* out = (float*)d_out;

    int n = in_sizes[0] / IN_F;
    int e = in_sizes[1] / 2;
    int nb = (n + 1023) / 1024;

    k_init_deg<<<(n + 255) / 256, 256>>>(n);
    k_hist<<<(e + 255) / 256, 256>>>(ei, e);
    k_aux<<<(n + 255) / 256, 256>>>(n);
    k_blocksum<<<nb, 1024>>>(n);
    k_scanbsums<<<1, 32>>>(nb);
    k_scanlocal<<<nb, 1024>>>(n, e + n);
    k_scatter<<<(e + n + 255) / 256, 256>>>(ei, e, n);

    k_gemm1<<<(n + 63) / 64, 256>>>(x, W1, b1, g1, be1, n);

    int wgrid = (n + 7) / 8;
    int dir = 0;
    for (int j = 1; j <= 10; j++) {
        k_spmm<<<wgrid, 256>>>(dir, n);
        int curInB = (dir == 0);
        dir ^= 1;
        if (j == 6)  k_mix<<<(n + 63) / 64, 256>>>(curInB, Wc + 6 * HID * HID,  bc + 6 * HID,  0,   n);
        if (j == 8)  k_mix<<<(n + 63) / 64, 256>>>(curInB, Wc + 8 * HID * HID,  bc + 8 * HID,  64,  n);
        if (j == 10) k_mix<<<(n + 63) / 64, 256>>>(curInB, Wc + 10 * HID * HID, bc + 10 * HID, 128, n);
    }

    k_final<<<wgrid, 256>>>(W2, b2, g2, be2, out, n);
}